// round 15
// baseline (speedup 1.0000x reference)
#include <cuda_runtime.h>
#include <cuda_fp16.h>
#include <cstdint>

#define TOKENS 64
#define IN_F   8192
#define OUT_F  8192
#define NGROUPS (IN_F / 8)     // 1024
#define KT_TILES (IN_F / 16)   // 512 k16 tiles
#define KSPLIT 4
#define NBLK   64              // N per block (4 warps x N16)
#define HALF_F 4096

// A fragments: [kt][mt][lane] -> uint4 (4 regs of m16k16 fp16 frag)
__device__ uint4 g_xa[KT_TILES * 4 * 32];            // 1 MB
// accumulated output [token][out] (REDG target, zeroed by fwht_in)
__device__ float g_acc[TOKENS * OUT_F];              // 2 MB
// readiness flags: chunk hb (kt<256 / kt>=256) -> #tokens published
__device__ int g_ready[2];

#define INV_SQRT_8192 0.011048543456039806f

__device__ __forceinline__ int SW(int i) {
    return (i & ~31) | ((i ^ (i >> 5)) & 31);
}
__device__ __forceinline__ int ld_vol(const int* p) {
    int v;
    asm volatile("ld.volatile.global.s32 %0, [%1];" : "=r"(v) : "l"(p));
    return v;
}

#define FWHT_REG(a, N)                                            \
    _Pragma("unroll")                                             \
    for (int h = 1; h < (N); h <<= 1) {                           \
        _Pragma("unroll")                                         \
        for (int i = 0; i < (N); i++) {                           \
            if (!(i & h)) {                                       \
                float u = a[i], v = a[i ^ h];                     \
                a[i] = u + v; a[i ^ h] = u - v;                   \
            }                                                     \
        }                                                         \
    }

#define FWHT4096_BODY(s, tid, a, c)                               \
    FWHT_REG(a, 16)                                               \
    _Pragma("unroll")                                             \
    for (int j = 0; j < 16; j++)                                  \
        s[SW(tid + 256 * j)] = a[j];                              \
    __syncthreads();                                              \
    {                                                             \
        const int lo = tid & 15, hi = tid >> 4;                   \
        float bb[16];                                             \
        _Pragma("unroll")                                         \
        for (int j = 0; j < 16; j++)                              \
            bb[j] = s[SW(hi * 256 + j * 16 + lo)];                \
        FWHT_REG(bb, 16)                                          \
        __syncthreads();                                          \
        _Pragma("unroll")                                         \
        for (int j = 0; j < 16; j++)                              \
            s[SW(hi * 256 + j * 16 + lo)] = bb[j];                \
    }                                                             \
    __syncthreads();                                              \
    _Pragma("unroll")                                             \
    for (int i = 0; i < 16; i++)                                  \
        c[i] = s[SW(tid * 16 + i)];                               \
    FWHT_REG(c, 16)

// ---------------------------------------------------------------------------
// Kernel A: zero g_acc slice + FWHT(x*SU)*scale -> fp16 A-fragments.
// 2 blocks per token. Publishes its kt-chunk via g_ready[hb].
// ---------------------------------------------------------------------------
__global__ __launch_bounds__(256) void fwht_in_kernel(
    const float* __restrict__ x,
    const float* __restrict__ SU,
    const float* __restrict__ Wscale)
{
    cudaTriggerProgrammaticLaunchCompletion();

    __shared__ float s[HALF_F];               // 16 KB
    const int t   = blockIdx.x >> 1;
    const int hb  = blockIdx.x & 1;
    const int tid = threadIdx.x;
    const float* xr = x + (size_t)t * IN_F;

    // zero this block's 16 KB slice of g_acc (4096 floats)
    {
        float4* z = (float4*)(g_acc + (size_t)blockIdx.x * 4096) + tid;
#pragma unroll
        for (int v = 0; v < 4; v++)
            z[v * 256] = make_float4(0.f, 0.f, 0.f, 0.f);
    }

    float a[16];
#pragma unroll
    for (int j = 0; j < 16; j++) {
        const int i = tid + 256 * j;
        const float v0 = xr[i] * SU[i];
        const float v1 = xr[i + HALF_F] * SU[i + HALF_F];
        a[j] = hb ? (v0 - v1) : (v0 + v1);
    }

    float c[16];
    FWHT4096_BODY(s, tid, a, c)

    const float scale = INV_SQRT_8192 * Wscale[0];
    const int mt   = t >> 4;
    const int mrow = t & 15;
    const int kt   = hb * 256 + tid;          // this thread's k16 tile
    uint32_t* xa = (uint32_t*)g_xa;
#pragma unroll
    for (int p = 0; p < 8; p++) {
        const int r    = p >> 2;
        const int lane = ((mrow & 7) << 2) | (p & 3);
        const int reg  = (r << 1) | (mrow >> 3);
        __half2 h = __floats2half2_rn(c[2 * p] * scale, c[2 * p + 1] * scale);
        xa[(((kt * 4 + mt) * 32 + lane) << 2) + reg] = *(uint32_t*)&h;
    }

    __syncthreads();
    if (tid == 0) {
        __threadfence();                       // release g_xa chunk + g_acc zeroes
        atomicAdd(&g_ready[hb], 1);
    }
}

// ---------------------------------------------------------------------------
// Kernel B: fused codebook-decode + fp16 mma.sync GEMM.
// __launch_bounds__(128, 4): cap regs at 125 so 4 blocks/SM -> 592 slots
// -> the 512-block grid runs in ONE wave (kill the 68-block tail wave).
// ---------------------------------------------------------------------------
__device__ __forceinline__ void mma16816(float c[4], const uint4& a,
                                         uint32_t b0, uint32_t b1)
{
    asm volatile(
        "mma.sync.aligned.m16n8k16.row.col.f32.f16.f16.f32 "
        "{%0,%1,%2,%3},{%4,%5,%6,%7},{%8,%9},{%0,%1,%2,%3};\n"
        : "+f"(c[0]), "+f"(c[1]), "+f"(c[2]), "+f"(c[3])
        : "r"(a.x), "r"(a.y), "r"(a.z), "r"(a.w), "r"(b0), "r"(b1));
}

__global__ __launch_bounds__(128, 4) void gemm_kernel(
    const int*   __restrict__ Qidxs,
    const float* __restrict__ grid)
{
    __shared__ uint32_t cb[256 * 4];     // codebook as half2: [code][pair]
    const int tid = threadIdx.x;
    // prologue (independent of fwht_in)
    for (int i = tid; i < 1024; i += 128) {
        int c = i >> 2, j = i & 3;
        __half2 h = __floats2half2_rn(grid[c * 8 + 2 * j], grid[c * 8 + 2 * j + 1]);
        cb[i] = *(uint32_t*)&h;
    }

    const int lane = tid & 31;
    const int w    = tid >> 5;
    const int l4   = lane & 3;
    const int lq   = lane >> 2;
    const int oW   = blockIdx.x * NBLK + w * 16;
    const int split = blockIdx.y;

    const int ktBase = split * (KT_TILES / KSPLIT);   // 128 tiles per split
    const int ktEnd  = ktBase + (KT_TILES / KSPLIT);

    const int2* qp0 = (const int2*)(Qidxs + (size_t)(oW + lq) * NGROUPS);
    const int2* qp1 = (const int2*)(Qidxs + (size_t)(oW + 8 + lq) * NGROUPS);

    // Qidxs prefetch (independent of fwht_in)
    int2 qB[2][2];
    qB[0][0] = qp0[ktBase];     qB[0][1] = qp1[ktBase];
    qB[1][0] = qp0[ktBase + 1]; qB[1][1] = qp1[ktBase + 1];

    float acc[2][4][4];
#pragma unroll
    for (int n = 0; n < 2; n++)
#pragma unroll
        for (int m = 0; m < 4; m++)
#pragma unroll
            for (int r = 0; r < 4; r++) acc[n][m][r] = 0.0f;

    // wait for THIS split's kt-chunk
    if (tid == 0) {
        const int chunk = split >> 1;            // kt<256 -> 0, else 1
        while (ld_vol(&g_ready[chunk]) < TOKENS) __nanosleep(100);
    }
    __syncthreads();                             // cb visible + chunk ready

    uint4 aB[2][4];
#pragma unroll
    for (int m = 0; m < 4; m++) {
        aB[0][m] = g_xa[((ktBase    ) * 4 + m) * 32 + lane];
        aB[1][m] = g_xa[((ktBase + 1) * 4 + m) * 32 + lane];
    }

    for (int kt = ktBase; kt < ktEnd; kt += 2) {
        {
            const uint32_t b00 = cb[(qB[0][0].x << 2) | l4];
            const uint32_t b01 = cb[(qB[0][0].y << 2) | l4];
            const uint32_t b10 = cb[(qB[0][1].x << 2) | l4];
            const uint32_t b11 = cb[(qB[0][1].y << 2) | l4];
#pragma unroll
            for (int m = 0; m < 4; m++) {
                mma16816(acc[0][m], aB[0][m], b00, b01);
                mma16816(acc[1][m], aB[0][m], b10, b11);
            }
            const int ktn = (kt + 2 < ktEnd) ? kt + 2 : ktEnd - 1;
#pragma unroll
            for (int m = 0; m < 4; m++)
                aB[0][m] = g_xa[(ktn * 4 + m) * 32 + lane];
            qB[0][0] = qp0[ktn];
            qB[0][1] = qp1[ktn];
        }
        {
            const uint32_t b00 = cb[(qB[1][0].x << 2) | l4];
            const uint32_t b01 = cb[(qB[1][0].y << 2) | l4];
            const uint32_t b10 = cb[(qB[1][1].x << 2) | l4];
            const uint32_t b11 = cb[(qB[1][1].y << 2) | l4];
#pragma unroll
            for (int m = 0; m < 4; m++) {
                mma16816(acc[0][m], aB[1][m], b00, b01);
                mma16816(acc[1][m], aB[1][m], b10, b11);
            }
            const int ktn = (kt + 3 < ktEnd) ? kt + 3 : ktEnd - 1;
#pragma unroll
            for (int m = 0; m < 4; m++)
                aB[1][m] = g_xa[(ktn * 4 + m) * 32 + lane];
            qB[1][0] = qp0[ktn];
            qB[1][1] = qp1[ktn];
        }
    }

    // full wait (guards g_acc zeroing) -- trivially satisfied by now
    if (tid == 0) {
        while (ld_vol(&g_ready[0]) < TOKENS ||
               ld_vol(&g_ready[1]) < TOKENS) __nanosleep(100);
    }
    __syncthreads();

    // epilogue: REDG accumulate
#pragma unroll
    for (int n = 0; n < 2; n++) {
        const int o = oW + n * 8 + 2 * l4;
#pragma unroll
        for (int m = 0; m < 4; m++) {
            const int t0 = m * 16 + lq;
            atomicAdd(&g_acc[(size_t)t0 * OUT_F + o],           acc[n][m][0]);
            atomicAdd(&g_acc[(size_t)t0 * OUT_F + o + 1],       acc[n][m][1]);
            atomicAdd(&g_acc[(size_t)(t0 + 8) * OUT_F + o],     acc[n][m][2]);
            atomicAdd(&g_acc[(size_t)(t0 + 8) * OUT_F + o + 1], acc[n][m][3]);
        }
    }

    cudaTriggerProgrammaticLaunchCompletion();
}

// ---------------------------------------------------------------------------
// Kernel C: read accumulated g_acc (folded stride-4096 butterfly),
// FWHT_4096, * SV/sqrt + bias. 2 blocks per token. PDL consumer.
// Resets g_ready for the next graph replay.
// ---------------------------------------------------------------------------
__global__ __launch_bounds__(256) void fwht_out_kernel(
    const float* __restrict__ SV,
    const float* __restrict__ bias,
    float* __restrict__ out)
{
    __shared__ float s[HALF_F];
    const int t   = blockIdx.x >> 1;
    const int hb  = blockIdx.x & 1;
    const int tid = threadIdx.x;

    cudaGridDependencySynchronize();

    if (blockIdx.x == 0 && tid == 0) {
        g_ready[0] = 0;
        g_ready[1] = 0;
    }

    const float* row = g_acc + (size_t)t * OUT_F;
    float a[16];
#pragma unroll
    for (int j = 0; j < 16; j++) {
        const int i = tid + 256 * j;
        const float v0 = row[i];
        const float v1 = row[i + HALF_F];
        a[j] = hb ? (v0 - v1) : (v0 + v1);
    }

    float c[16];
    FWHT4096_BODY(s, tid, a, c)

    float* orow = out + (size_t)t * OUT_F + hb * HALF_F;
#pragma unroll
    for (int i = 0; i < 16; i++) {
        const int idx = tid * 16 + i;
        const int gidx = hb * HALF_F + idx;
        orow[idx] = c[i] * INV_SQRT_8192 * SV[gidx] + bias[gidx];
    }
}

// ---------------------------------------------------------------------------
// Inputs (metadata order): x, SU, SV, grid, Wscale, bias, Qidxs
// ---------------------------------------------------------------------------
extern "C" void kernel_launch(void* const* d_in, const int* in_sizes, int n_in,
                              void* d_out, int out_size)
{
    const float* x      = (const float*)d_in[0];
    const float* SU     = (const float*)d_in[1];
    const float* SV     = (const float*)d_in[2];
    const float* grid   = (const float*)d_in[3];
    const float* Wscale = (const float*)d_in[4];
    const float* bias   = (const float*)d_in[5];
    const int*   Qidxs  = (const int*)  d_in[6];
    float*       out    = (float*)d_out;

    fwht_in_kernel<<<2 * TOKENS, 256>>>(x, SU, Wscale);

    {
        cudaLaunchConfig_t cfg = {};
        cfg.gridDim  = dim3(OUT_F / NBLK, KSPLIT, 1);
        cfg.blockDim = dim3(128, 1, 1);
        cudaLaunchAttribute attr[1];
        attr[0].id = cudaLaunchAttributeProgrammaticStreamSerialization;
        attr[0].val.programmaticStreamSerializationAllowed = 1;
        cfg.attrs = attr;
        cfg.numAttrs = 1;
        cudaLaunchKernelEx(&cfg, gemm_kernel, Qidxs, grid);
    }

    {
        cudaLaunchConfig_t cfg = {};
        cfg.gridDim  = dim3(2 * TOKENS, 1, 1);
        cfg.blockDim = dim3(256, 1, 1);
        cudaLaunchAttribute attr[1];
        attr[0].id = cudaLaunchAttributeProgrammaticStreamSerialization;
        attr[0].val.programmaticStreamSerializationAllowed = 1;
        cfg.attrs = attr;
        cfg.numAttrs = 1;
        cudaLaunchKernelEx(&cfg, fwht_out_kernel, SV, bias, out);
    }
}